// round 1
// baseline (speedup 1.0000x reference)
#include <cuda_runtime.h>

#define NN 100000
#define EE 1600000
#define HH 32
#define CC 10
#define GG 64

// ---------------- scratch (static device globals; no allocation) ----------------
__device__ int   d_cnt[NN];
__device__ int   d_off[NN + 1];
__device__ int   d_rows[EE];
__device__ float d_dinv[NN];
__device__ float d_A[NN * HH];
__device__ float d_B[NN * HH];
__device__ float d_xw1[NN * HH];
__device__ float d_y[NN * HH];
__device__ float d_h1[NN * HH];
__device__ float d_xw2[NN * HH];
__device__ float d_pooled[GG * HH];
__device__ float d_gcnt[GG];
__device__ float d_P[CC * 3 * HH];
__device__ float d_Q[CC * 3 * HH];
__device__ float d_pb[CC * HH];
__device__ float d_qb[CC * HH];
__device__ float d_Gm[CC * HH * HH];
__device__ float d_biasE[HH];

// ---------------- small setup: fold weights ----------------
// P_c = filt_W[c] @ W1[0:32],  Q_c = filt_W[c] @ W1[32:64]   (3x32 each)
// pb_c = filt_b[c] @ W1[0:32], qb_c = filt_b[c] @ W1[32:64] + mlp_b1
// Gm_c = mlp_W2 @ gcn1_W[3+32c : 3+32c+32]                   (32x32)
// biasE = sum_c mlp_b2 @ gcn1_W[3+32c : 3+32c+32]
__global__ void setup_k(const float* __restrict__ fW, const float* __restrict__ fb,
                        const float* __restrict__ W1, const float* __restrict__ b1,
                        const float* __restrict__ W2, const float* __restrict__ b2,
                        const float* __restrict__ g1W) {
    int stride = blockDim.x * gridDim.x;
    int tid0 = threadIdx.x + blockIdx.x * blockDim.x;
    for (int t = tid0; t < CC * 3 * HH; t += stride) {
        int c = t / (3 * HH); int i = (t / HH) % 3; int h = t % HH;
        float sa = 0.f, sb = 0.f;
        for (int j = 0; j < HH; j++) {
            float w = fW[(c * 3 + i) * HH + j];
            sa += w * W1[j * HH + h];
            sb += w * W1[(HH + j) * HH + h];
        }
        d_P[t] = sa; d_Q[t] = sb;
    }
    for (int t = tid0; t < CC * HH; t += stride) {
        int c = t / HH; int h = t % HH;
        float sa = 0.f, sb = 0.f;
        for (int j = 0; j < HH; j++) {
            float bv = fb[c * HH + j];
            sa += bv * W1[j * HH + h];
            sb += bv * W1[(HH + j) * HH + h];
        }
        d_pb[t] = sa; d_qb[t] = sb + b1[h];
    }
    for (int t = tid0; t < CC * HH * HH; t += stride) {
        int c = t / (HH * HH); int i = (t / HH) % HH; int j = t % HH;
        float s = 0.f;
        for (int k = 0; k < HH; k++) s += W2[i * HH + k] * g1W[(3 + HH * c + k) * HH + j];
        d_Gm[t] = s;
    }
    for (int t = tid0; t < HH; t += stride) {
        float s = 0.f;
        for (int c = 0; c < CC; c++)
            for (int k = 0; k < HH; k++) s += b2[k] * g1W[(3 + HH * c + k) * HH + t];
        d_biasE[t] = s;
    }
}

// ---------------- zeroing kernels (no memset API needed) ----------------
__global__ void zero1_k() {
    int t = threadIdx.x + blockIdx.x * blockDim.x;
    int stride = blockDim.x * gridDim.x;
    for (int i = t; i < NN; i += stride) d_cnt[i] = 0;
    for (int i = t; i < GG * HH; i += stride) d_pooled[i] = 0.f;
    for (int i = t; i < GG; i += stride) d_gcnt[i] = 0.f;
}
__global__ void zero2_k() {
    int t = threadIdx.x + blockIdx.x * blockDim.x;
    int stride = blockDim.x * gridDim.x;
    for (int i = t; i < NN; i += stride) d_cnt[i] = 0;
}

// ---------------- CSR build ----------------
__global__ void hist_k(const int* __restrict__ col) {
    int t = threadIdx.x + blockIdx.x * blockDim.x;
    int stride = blockDim.x * gridDim.x;
    for (int e = t; e < EE; e += stride) atomicAdd(&d_cnt[col[e]], 1);
}
__global__ void gcount_k(const int* __restrict__ batch) {
    int t = threadIdx.x + blockIdx.x * blockDim.x;
    int stride = blockDim.x * gridDim.x;
    for (int n = t; n < NN; n += stride) atomicAdd(&d_gcnt[batch[n]], 1.0f);
}

// single-block scan over d_cnt -> exclusive offsets d_off, and dinv = rsqrt(indeg+1)
__global__ void scan_k() {
    __shared__ int wsum[32];
    __shared__ int carry_sh;
    int tid = threadIdx.x, lane = tid & 31, w = tid >> 5;
    if (tid == 0) carry_sh = 0;
    __syncthreads();
    for (int base = 0; base < NN; base += 1024) {
        int i = base + tid;
        int v = (i < NN) ? d_cnt[i] : 0;
        int s = v;
        #pragma unroll
        for (int d = 1; d < 32; d <<= 1) {
            int tt = __shfl_up_sync(0xffffffffu, s, d);
            if (lane >= d) s += tt;
        }
        if (lane == 31) wsum[w] = s;
        __syncthreads();
        if (w == 0) {
            int t2 = wsum[lane];
            #pragma unroll
            for (int d = 1; d < 32; d <<= 1) {
                int u = __shfl_up_sync(0xffffffffu, t2, d);
                if (lane >= d) t2 += u;
            }
            wsum[lane] = t2;
        }
        __syncthreads();
        int offset = carry_sh + (w > 0 ? wsum[w - 1] : 0);
        if (i < NN) {
            d_off[i] = offset + s - v;
            d_dinv[i] = rsqrtf((float)(v + 1));
        }
        __syncthreads();
        if (tid == 1023) carry_sh = offset + s;
        __syncthreads();
    }
    if (tid == 0) d_off[NN] = carry_sh;
}

__global__ void fill_k(const int* __restrict__ row, const int* __restrict__ col) {
    int t = threadIdx.x + blockIdx.x * blockDim.x;
    int stride = blockDim.x * gridDim.x;
    for (int e = t; e < EE; e += stride) {
        int cn = col[e];
        int pos = atomicAdd(&d_cnt[cn], 1);
        d_rows[d_off[cn] + pos] = row[e];
    }
}

// ---------------- xw1 init: x @ gcn1_W[0:3] + indeg * biasE ----------------
__global__ void init_xw1_k(const float* __restrict__ x, const float* __restrict__ g1W) {
    int t = threadIdx.x + blockIdx.x * blockDim.x;
    if (t >= NN * HH) return;
    int n = t >> 5; int h = t & 31;
    float indeg = (float)(d_off[n + 1] - d_off[n]);
    float s = x[n * 3 + 0] * g1W[0 * HH + h]
            + x[n * 3 + 1] * g1W[1 * HH + h]
            + x[n * 3 + 2] * g1W[2 * HH + h]
            + indeg * d_biasE[h];
    d_xw1[t] = s;
}

// ---------------- per-class A/B node features ----------------
__global__ void ab_k(const float* __restrict__ x, int c) {
    int t = threadIdx.x + blockIdx.x * blockDim.x;
    if (t >= NN * HH) return;
    int n = t >> 5; int h = t & 31;
    float x0 = x[n * 3 + 0], x1 = x[n * 3 + 1], x2 = x[n * 3 + 2];
    const float* P = d_P + c * 3 * HH;
    const float* Q = d_Q + c * 3 * HH;
    d_A[t] = x0 * P[0 * HH + h] + x1 * P[1 * HH + h] + x2 * P[2 * HH + h] + d_pb[c * HH + h];
    d_B[t] = x0 * Q[0 * HH + h] + x1 * Q[1 * HH + h] + x2 * Q[2 * HH + h] + d_qb[c * HH + h];
}

// ---------------- per-class edge aggregation: warp per node ----------------
// Rsum[n] = sum_{e in col==n} relu(A[row_e] + B[n]);  xw1[n] += Rsum[n] @ Gm_c
__global__ void edge_agg_k(int c) {
    __shared__ float Gs[HH * HH];
    for (int t = threadIdx.x; t < HH * HH; t += blockDim.x) Gs[t] = d_Gm[c * HH * HH + t];
    __syncthreads();
    int lane = threadIdx.x & 31;
    int n = blockIdx.x * (blockDim.x >> 5) + (threadIdx.x >> 5);
    if (n >= NN) return;
    int base = d_off[n], end = d_off[n + 1];
    float Bn = d_B[n * HH + lane];
    float a0 = 0.f, a1 = 0.f, a2 = 0.f, a3 = 0.f;
    int k = base;
    for (; k + 4 <= end; k += 4) {
        int r0 = d_rows[k + 0], r1 = d_rows[k + 1], r2 = d_rows[k + 2], r3 = d_rows[k + 3];
        a0 += fmaxf(d_A[r0 * HH + lane] + Bn, 0.f);
        a1 += fmaxf(d_A[r1 * HH + lane] + Bn, 0.f);
        a2 += fmaxf(d_A[r2 * HH + lane] + Bn, 0.f);
        a3 += fmaxf(d_A[r3 * HH + lane] + Bn, 0.f);
    }
    for (; k < end; k++) {
        int r = d_rows[k];
        a0 += fmaxf(d_A[r * HH + lane] + Bn, 0.f);
    }
    float acc = (a0 + a1) + (a2 + a3);
    float out = 0.f;
    #pragma unroll
    for (int i = 0; i < HH; i++)
        out += __shfl_sync(0xffffffffu, acc, i) * Gs[i * HH + lane];
    d_xw1[n * HH + lane] += out;
}

// ---------------- GCN layer 1 ----------------
__global__ void y1_k() {
    int t = threadIdx.x + blockIdx.x * blockDim.x;
    if (t >= NN * HH) return;
    d_y[t] = d_xw1[t] * d_dinv[t >> 5];
}
__global__ void gcn1_k(const float* __restrict__ g1b) {
    int lane = threadIdx.x & 31;
    int n = blockIdx.x * (blockDim.x >> 5) + (threadIdx.x >> 5);
    if (n >= NN) return;
    int base = d_off[n], end = d_off[n + 1];
    float a0 = 0.f, a1 = 0.f, a2 = 0.f, a3 = 0.f;
    int k = base;
    for (; k + 4 <= end; k += 4) {
        int r0 = d_rows[k + 0], r1 = d_rows[k + 1], r2 = d_rows[k + 2], r3 = d_rows[k + 3];
        a0 += d_y[r0 * HH + lane]; a1 += d_y[r1 * HH + lane];
        a2 += d_y[r2 * HH + lane]; a3 += d_y[r3 * HH + lane];
    }
    for (; k < end; k++) a0 += d_y[d_rows[k] * HH + lane];
    float acc = (a0 + a1) + (a2 + a3);
    float dv = d_dinv[n];
    float v = dv * acc + dv * dv * d_xw1[n * HH + lane] + g1b[lane];
    d_h1[n * HH + lane] = fmaxf(v, 0.f);
}

// ---------------- GCN layer 2 matmul (xw2 = h1 @ gcn2_W; y = xw2*dinv) ----------------
__global__ void xw2_k(const float* __restrict__ g2W) {
    __shared__ float Ws[HH * HH];
    for (int t = threadIdx.x; t < HH * HH; t += blockDim.x) Ws[t] = g2W[t];
    __syncthreads();
    int t = threadIdx.x + blockIdx.x * blockDim.x;
    if (t >= NN * HH) return;
    int n = t >> 5; int j = t & 31;
    const float* h = d_h1 + n * HH;
    float s = 0.f;
    #pragma unroll
    for (int kk = 0; kk < HH; kk++) s += h[kk] * Ws[kk * HH + j];
    d_xw2[t] = s;
    d_y[t] = s * d_dinv[n];
}

// ---------------- GCN layer 2 gather + pooling ----------------
__global__ void gcn2_pool_k(const float* __restrict__ g2b, const int* __restrict__ batch) {
    int lane = threadIdx.x & 31;
    int n = blockIdx.x * (blockDim.x >> 5) + (threadIdx.x >> 5);
    if (n >= NN) return;
    int base = d_off[n], end = d_off[n + 1];
    float a0 = 0.f, a1 = 0.f, a2 = 0.f, a3 = 0.f;
    int k = base;
    for (; k + 4 <= end; k += 4) {
        int r0 = d_rows[k + 0], r1 = d_rows[k + 1], r2 = d_rows[k + 2], r3 = d_rows[k + 3];
        a0 += d_y[r0 * HH + lane]; a1 += d_y[r1 * HH + lane];
        a2 += d_y[r2 * HH + lane]; a3 += d_y[r3 * HH + lane];
    }
    for (; k < end; k++) a0 += d_y[d_rows[k] * HH + lane];
    float acc = (a0 + a1) + (a2 + a3);
    float dv = d_dinv[n];
    float v = fmaxf(dv * acc + dv * dv * d_xw2[n * HH + lane] + g2b[lane], 0.f);
    atomicAdd(&d_pooled[batch[n] * HH + lane], v);
}

// ---------------- classifier ----------------
__global__ void classify_k(const float* __restrict__ clsW, const float* __restrict__ clsb,
                           float* __restrict__ out) {
    int t = threadIdx.x + blockIdx.x * blockDim.x;
    if (t >= GG * CC) return;
    int g = t / CC; int j = t % CC;
    float cnt = fmaxf(d_gcnt[g], 1.0f);
    float inv = 1.0f / cnt;
    float s = clsb[j];
    #pragma unroll
    for (int k = 0; k < HH; k++) s += d_pooled[g * HH + k] * inv * clsW[k * CC + j];
    out[t] = s;
}

// ---------------- launch ----------------
extern "C" void kernel_launch(void* const* d_in, const int* in_sizes, int n_in,
                              void* d_out, int out_size) {
    const float* x     = (const float*)d_in[0];
    const int*   ei    = (const int*)d_in[1];
    const int*   row   = ei;
    const int*   col   = ei + EE;
    const int*   batch = (const int*)d_in[2];
    const float* fW    = (const float*)d_in[3];
    const float* fb    = (const float*)d_in[4];
    const float* W1    = (const float*)d_in[5];
    const float* b1    = (const float*)d_in[6];
    const float* W2    = (const float*)d_in[7];
    const float* b2    = (const float*)d_in[8];
    const float* g1W   = (const float*)d_in[9];
    const float* g1b   = (const float*)d_in[10];
    const float* g2W   = (const float*)d_in[11];
    const float* g2b   = (const float*)d_in[12];
    const float* clsW  = (const float*)d_in[13];
    const float* clsb  = (const float*)d_in[14];
    float* out = (float*)d_out;

    const int TB = 256;
    const int gridNH = (NN * HH + TB - 1) / TB;           // elementwise over N*32
    const int gridWarpNode = (NN + (TB / 32) - 1) / (TB / 32);  // warp per node
    const int gridE = (EE + TB - 1) / TB > 2048 ? 2048 : (EE + TB - 1) / TB;

    setup_k<<<40, 256>>>(fW, fb, W1, b1, W2, b2, g1W);
    zero1_k<<<256, 256>>>();
    hist_k<<<gridE, TB>>>(col);
    gcount_k<<<256, TB>>>(batch);
    scan_k<<<1, 1024>>>();
    zero2_k<<<256, 256>>>();
    fill_k<<<gridE, TB>>>(row, col);
    init_xw1_k<<<gridNH, TB>>>(x, g1W);

    for (int c = 0; c < CC; c++) {
        ab_k<<<gridNH, TB>>>(x, c);
        edge_agg_k<<<gridWarpNode, TB>>>(c);
    }

    y1_k<<<gridNH, TB>>>();
    gcn1_k<<<gridWarpNode, TB>>>(g1b);
    xw2_k<<<gridNH, TB>>>(g2W);
    gcn2_pool_k<<<gridWarpNode, TB>>>(g2b, batch);
    classify_k<<<(GG * CC + TB - 1) / TB, TB>>>(clsW, clsb, out);
}

// round 2
// speedup vs baseline: 2.2166x; 2.2166x over previous
#include <cuda_runtime.h>

#define NN 100000
#define EE 1600000
#define HH 32
#define CC 10
#define GG 64
#define NBLK 98   // ceil(NN/1024)

typedef unsigned long long ull;

// ---------------- packed f32x2 helpers ----------------
__device__ __forceinline__ ull pack2(float lo, float hi) {
    ull r; asm("mov.b64 %0,{%1,%2};" : "=l"(r) : "f"(lo), "f"(hi)); return r;
}
__device__ __forceinline__ void unpack2(ull v, float& lo, float& hi) {
    asm("mov.b64 {%0,%1},%2;" : "=f"(lo), "=f"(hi) : "l"(v));
}
__device__ __forceinline__ ull fma2(ull a, ull b, ull c) {
    ull d; asm("fma.rn.f32x2 %0,%1,%2,%3;" : "=l"(d) : "l"(a), "l"(b), "l"(c)); return d;
}
__device__ __forceinline__ ull add2(ull a, ull b) {
    ull d; asm("add.rn.f32x2 %0,%1,%2;" : "=l"(d) : "l"(a), "l"(b)); return d;
}
__device__ __forceinline__ ull relu2(ull t) {
    float lo, hi; unpack2(t, lo, hi);
    lo = fmaxf(lo, 0.f); hi = fmaxf(hi, 0.f);
    return pack2(lo, hi);
}

// ---------------- scratch ----------------
__device__ int    d_cnt[NN];
__device__ int    d_cur[NN];
__device__ int    d_off[NN + 1];
__device__ int    d_rows[EE];
__device__ int    d_bsum[NBLK];
__device__ int    d_gstart[GG + 1];
__device__ float  d_dinv[NN];
__device__ float4 d_xpad[NN];
__device__ float  d_xw1[NN * HH];
__device__ float  d_y[NN * HH];
__device__ float  d_h1[NN * HH];
__device__ float  d_xw2[NN * HH];
__device__ float  d_h2[NN * HH];
__device__ ull    d_Ppk[5 * 3 * HH];
__device__ ull    d_Qpk[5 * 3 * HH];
__device__ ull    d_Cpk[5 * HH];
__device__ float  d_Gf[CC * HH * HH];   // [320][32]
__device__ float  d_biasE[HH];
__device__ float  d_Rs[NN * 320];       // 128MB scratch

// ---------------- setup: fold & pack weights ----------------
__global__ void setup_k(const float* __restrict__ fW, const float* __restrict__ fb,
                        const float* __restrict__ W1, const float* __restrict__ b1,
                        const float* __restrict__ W2, const float* __restrict__ b2,
                        const float* __restrict__ g1W) {
    int stride = blockDim.x * gridDim.x;
    int t0 = threadIdx.x + blockIdx.x * blockDim.x;
    // Ppk/Qpk: class-pair packed (3x32 per class)
    for (int t = t0; t < 5 * 3 * HH; t += stride) {
        int p = t / 96; int i = (t / 32) % 3; int h = t & 31;
        int c0 = 2 * p, c1 = 2 * p + 1;
        float pa0 = 0.f, pa1 = 0.f, qa0 = 0.f, qa1 = 0.f;
        for (int j = 0; j < HH; j++) {
            float w0 = fW[(c0 * 3 + i) * HH + j];
            float w1 = fW[(c1 * 3 + i) * HH + j];
            float u1 = W1[j * HH + h];
            float u2 = W1[(HH + j) * HH + h];
            pa0 += w0 * u1; pa1 += w1 * u1;
            qa0 += w0 * u2; qa1 += w1 * u2;
        }
        d_Ppk[t] = pack2(pa0, pa1);
        d_Qpk[t] = pack2(qa0, qa1);
    }
    // Cpk = pb + qb (qb includes b1), class-pair packed
    for (int t = t0; t < 5 * HH; t += stride) {
        int p = t / 32; int h = t & 31;
        int c0 = 2 * p, c1 = 2 * p + 1;
        float s0 = b1[h], s1 = b1[h];
        for (int j = 0; j < HH; j++) {
            float u = W1[j * HH + h] + W1[(HH + j) * HH + h];
            s0 += fb[c0 * HH + j] * u;
            s1 += fb[c1 * HH + j] * u;
        }
        d_Cpk[t] = pack2(s0, s1);
    }
    // Gf[c*32+i][j] = sum_k W2[i][k] * g1W[3+32c+k][j]
    for (int t = t0; t < CC * HH * HH; t += stride) {
        int c = t / (HH * HH); int i = (t / HH) % HH; int j = t & 31;
        float s = 0.f;
        for (int k = 0; k < HH; k++) s += W2[i * HH + k] * g1W[(3 + HH * c + k) * HH + j];
        d_Gf[t] = s;
    }
    for (int t = t0; t < HH; t += stride) {
        float s = 0.f;
        for (int c = 0; c < CC; c++)
            for (int k = 0; k < HH; k++) s += b2[k] * g1W[(3 + HH * c + k) * HH + t];
        d_biasE[t] = s;
    }
}

// ---------------- zero counters ----------------
__global__ void zero_k() {
    int t = threadIdx.x + blockIdx.x * blockDim.x;
    int stride = blockDim.x * gridDim.x;
    for (int i = t; i < NN; i += stride) { d_cnt[i] = 0; d_cur[i] = 0; }
}

// ---------------- CSR build ----------------
__global__ void hist_k(const int* __restrict__ col) {
    int e = threadIdx.x + blockIdx.x * blockDim.x;
    if (e < EE) atomicAdd(&d_cnt[col[e]], 1);
}

// graph boundaries via sortedness (zero atomics)
__global__ void gstart_k(const int* __restrict__ batch) {
    int n = threadIdx.x + blockIdx.x * blockDim.x;
    if (n >= NN) return;
    int g = batch[n];
    int gp = n ? batch[n - 1] : -1;
    if (g != gp) for (int q = gp + 1; q <= g; q++) d_gstart[q] = n;
    if (n == NN - 1) for (int q = g + 1; q <= GG; q++) d_gstart[q] = NN;
}

// 3-phase scan
__global__ void scanA_k() {
    __shared__ int wsum[32];
    int i = blockIdx.x * 1024 + threadIdx.x;
    int lane = threadIdx.x & 31, w = threadIdx.x >> 5;
    int v = (i < NN) ? d_cnt[i] : 0;
    #pragma unroll
    for (int d = 16; d > 0; d >>= 1) v += __shfl_down_sync(0xffffffffu, v, d);
    if (lane == 0) wsum[w] = v;
    __syncthreads();
    if (w == 0) {
        int s = wsum[lane];
        #pragma unroll
        for (int d = 16; d > 0; d >>= 1) s += __shfl_down_sync(0xffffffffu, s, d);
        if (lane == 0) d_bsum[blockIdx.x] = s;
    }
}
__global__ void scanB_k() {
    int lane = threadIdx.x;
    int carry = 0;
    for (int base = 0; base < NBLK; base += 32) {
        int i = base + lane;
        int v = (i < NBLK) ? d_bsum[i] : 0;
        int s = v;
        #pragma unroll
        for (int d = 1; d < 32; d <<= 1) {
            int u = __shfl_up_sync(0xffffffffu, s, d);
            if (lane >= d) s += u;
        }
        if (i < NBLK) d_bsum[i] = carry + s - v;
        carry += __shfl_sync(0xffffffffu, s, 31);
    }
}
__global__ void scanC_k() {
    __shared__ int wsum[32];
    int i = blockIdx.x * 1024 + threadIdx.x;
    int lane = threadIdx.x & 31, w = threadIdx.x >> 5;
    int v = (i < NN) ? d_cnt[i] : 0;
    int s = v;
    #pragma unroll
    for (int d = 1; d < 32; d <<= 1) {
        int u = __shfl_up_sync(0xffffffffu, s, d);
        if (lane >= d) s += u;
    }
    if (lane == 31) wsum[w] = s;
    __syncthreads();
    if (w == 0) {
        int t2 = wsum[lane];
        #pragma unroll
        for (int d = 1; d < 32; d <<= 1) {
            int u = __shfl_up_sync(0xffffffffu, t2, d);
            if (lane >= d) t2 += u;
        }
        wsum[lane] = t2;
    }
    __syncthreads();
    int base = d_bsum[blockIdx.x] + (w > 0 ? wsum[w - 1] : 0);
    if (i < NN) {
        d_off[i] = base + s - v;
        d_dinv[i] = rsqrtf((float)(v + 1));
    }
    if (i == NN - 1) d_off[NN] = base + s;
}

__global__ void fill_k(const int* __restrict__ row, const int* __restrict__ col) {
    int e = threadIdx.x + blockIdx.x * blockDim.x;
    if (e >= EE) return;
    int cn = col[e];
    int pos = atomicAdd(&d_cur[cn], 1);
    d_rows[d_off[cn] + pos] = row[e];
}

// ---------------- init: xpad + xw1 base ----------------
__global__ void init_k(const float* __restrict__ x, const float* __restrict__ g1W) {
    int t = threadIdx.x + blockIdx.x * blockDim.x;
    if (t >= NN * HH) return;
    int n = t >> 5; int h = t & 31;
    float x0 = x[n * 3 + 0], x1 = x[n * 3 + 1], x2 = x[n * 3 + 2];
    float indeg = (float)(d_off[n + 1] - d_off[n]);
    d_xw1[t] = x0 * g1W[h] + x1 * g1W[HH + h] + x2 * g1W[2 * HH + h] + indeg * d_biasE[h];
    if (h == 0) d_xpad[n] = make_float4(x0, x1, x2, 0.f);
}

// ---------------- fused 10-class edge MLP aggregation ----------------
// Rs[n][c*32+l] = sum_{e: col==n} relu(x_r . P_c[:,l] + x_n . Q_c[:,l] + C_c[l])
__global__ void __launch_bounds__(256) edge_k() {
    __shared__ ull Qs[5 * 3 * HH];
    __shared__ ull Cs[5 * HH];
    for (int t = threadIdx.x; t < 5 * 3 * HH; t += blockDim.x) Qs[t] = d_Qpk[t];
    for (int t = threadIdx.x; t < 5 * HH; t += blockDim.x) Cs[t] = d_Cpk[t];
    __syncthreads();

    int lane = threadIdx.x & 31;
    int gw = (blockIdx.x * blockDim.x + threadIdx.x) >> 5;
    int nw = (gridDim.x * blockDim.x) >> 5;

    ull P0[5], P1[5], P2[5];
    #pragma unroll
    for (int p = 0; p < 5; p++) {
        P0[p] = d_Ppk[(p * 3 + 0) * HH + lane];
        P1[p] = d_Ppk[(p * 3 + 1) * HH + lane];
        P2[p] = d_Ppk[(p * 3 + 2) * HH + lane];
    }

    for (int n = gw; n < NN; n += nw) {
        float4 xn = d_xpad[n];
        ull xn0 = pack2(xn.x, xn.x), xn1 = pack2(xn.y, xn.y), xn2 = pack2(xn.z, xn.z);
        ull B[5], acc[5];
        #pragma unroll
        for (int p = 0; p < 5; p++) {
            ull b = fma2(xn0, Qs[(p * 3 + 0) * HH + lane], Cs[p * HH + lane]);
            b = fma2(xn1, Qs[(p * 3 + 1) * HH + lane], b);
            b = fma2(xn2, Qs[(p * 3 + 2) * HH + lane], b);
            B[p] = b;
            acc[p] = pack2(0.f, 0.f);
        }
        int k = d_off[n], ke = d_off[n + 1];
        for (; k + 2 <= ke; k += 2) {
            int r0 = __ldg(&d_rows[k]);
            int r1 = __ldg(&d_rows[k + 1]);
            float4 a = d_xpad[r0];
            float4 b4 = d_xpad[r1];
            ull a0 = pack2(a.x, a.x), a1 = pack2(a.y, a.y), a2 = pack2(a.z, a.z);
            ull c0 = pack2(b4.x, b4.x), c1 = pack2(b4.y, b4.y), c2 = pack2(b4.z, b4.z);
            #pragma unroll
            for (int p = 0; p < 5; p++) {
                ull t = fma2(a0, P0[p], B[p]);
                t = fma2(a1, P1[p], t);
                t = fma2(a2, P2[p], t);
                acc[p] = add2(acc[p], relu2(t));
                ull u = fma2(c0, P0[p], B[p]);
                u = fma2(c1, P1[p], u);
                u = fma2(c2, P2[p], u);
                acc[p] = add2(acc[p], relu2(u));
            }
        }
        if (k < ke) {
            int r0 = __ldg(&d_rows[k]);
            float4 a = d_xpad[r0];
            ull a0 = pack2(a.x, a.x), a1 = pack2(a.y, a.y), a2 = pack2(a.z, a.z);
            #pragma unroll
            for (int p = 0; p < 5; p++) {
                ull t = fma2(a0, P0[p], B[p]);
                t = fma2(a1, P1[p], t);
                t = fma2(a2, P2[p], t);
                acc[p] = add2(acc[p], relu2(t));
            }
        }
        float* rs = d_Rs + n * 320;
        #pragma unroll
        for (int p = 0; p < 5; p++) {
            float lo, hi; unpack2(acc[p], lo, hi);
            rs[(2 * p) * HH + lane] = lo;
            rs[(2 * p + 1) * HH + lane] = hi;
        }
    }
}

// ---------------- tiled GEMM: xw1 += Rs[N,320] @ Gf[320,32]; y = xw1*dinv ----------------
#define KC 32
__global__ void __launch_bounds__(256) gemm_k() {
    __shared__ float As[256][KC + 1];   // ~33KB
    __shared__ float Gsh[KC][HH];       // 4KB
    int t = threadIdx.x;
    int warp = t >> 5, lane = t & 31;
    int tx = t & 7, ty = t >> 3;
    int n0 = blockIdx.x * 256;
    ull acc[8][2];
    #pragma unroll
    for (int m = 0; m < 8; m++) { acc[m][0] = pack2(0.f, 0.f); acc[m][1] = pack2(0.f, 0.f); }

    for (int kc = 0; kc < 320; kc += KC) {
        __syncthreads();
        for (int i = t; i < KC * HH; i += 256)
            Gsh[i >> 5][i & 31] = d_Gf[(kc + (i >> 5)) * HH + (i & 31)];
        for (int it = 0; it < 32; it++) {
            int nl = warp * 32 + it;
            int n = n0 + nl;
            As[nl][lane] = (n < NN) ? d_Rs[n * 320 + kc + lane] : 0.f;
        }
        __syncthreads();
        #pragma unroll 8
        for (int kk = 0; kk < KC; kk++) {
            float4 g4 = *(const float4*)&Gsh[kk][tx * 4];
            ull g0 = pack2(g4.x, g4.y), g1 = pack2(g4.z, g4.w);
            #pragma unroll
            for (int m = 0; m < 8; m++) {
                float a = As[ty * 8 + m][kk];
                ull ap = pack2(a, a);
                acc[m][0] = fma2(ap, g0, acc[m][0]);
                acc[m][1] = fma2(ap, g1, acc[m][1]);
            }
        }
    }
    #pragma unroll
    for (int m = 0; m < 8; m++) {
        int n = n0 + ty * 8 + m;
        if (n < NN) {
            float o0, o1, o2, o3;
            unpack2(acc[m][0], o0, o1);
            unpack2(acc[m][1], o2, o3);
            float4 cur = *(const float4*)&d_xw1[n * HH + tx * 4];
            o0 += cur.x; o1 += cur.y; o2 += cur.z; o3 += cur.w;
            *(float4*)&d_xw1[n * HH + tx * 4] = make_float4(o0, o1, o2, o3);
            float dv = d_dinv[n];
            *(float4*)&d_y[n * HH + tx * 4] = make_float4(o0 * dv, o1 * dv, o2 * dv, o3 * dv);
        }
    }
}

// ---------------- GCN layer 1 gather ----------------
__global__ void gcn1_k(const float* __restrict__ g1b) {
    int lane = threadIdx.x & 31;
    int n = blockIdx.x * (blockDim.x >> 5) + (threadIdx.x >> 5);
    if (n >= NN) return;
    int base = d_off[n], end = d_off[n + 1];
    float a0 = 0.f, a1 = 0.f, a2 = 0.f, a3 = 0.f;
    int k = base;
    for (; k + 4 <= end; k += 4) {
        int r0 = __ldg(&d_rows[k + 0]), r1 = __ldg(&d_rows[k + 1]);
        int r2 = __ldg(&d_rows[k + 2]), r3 = __ldg(&d_rows[k + 3]);
        a0 += d_y[r0 * HH + lane]; a1 += d_y[r1 * HH + lane];
        a2 += d_y[r2 * HH + lane]; a3 += d_y[r3 * HH + lane];
    }
    for (; k < end; k++) a0 += d_y[__ldg(&d_rows[k]) * HH + lane];
    float acc = (a0 + a1) + (a2 + a3);
    float dv = d_dinv[n];
    float v = dv * acc + dv * dv * d_xw1[n * HH + lane] + g1b[lane];
    d_h1[n * HH + lane] = fmaxf(v, 0.f);
}

// ---------------- xw2 = h1 @ gcn2_W; y = xw2*dinv ----------------
__global__ void xw2_k(const float* __restrict__ g2W) {
    __shared__ float Ws[HH * HH];
    for (int t = threadIdx.x; t < HH * HH; t += blockDim.x) Ws[t] = g2W[t];
    __syncthreads();
    int t = threadIdx.x + blockIdx.x * blockDim.x;
    if (t >= NN * HH) return;
    int n = t >> 5; int j = t & 31;
    const float* h = d_h1 + n * HH;
    float s = 0.f;
    #pragma unroll
    for (int kk = 0; kk < HH; kk++) s += h[kk] * Ws[kk * HH + j];
    d_xw2[t] = s;
    d_y[t] = s * d_dinv[n];
}

// ---------------- GCN layer 2 gather -> h2 ----------------
__global__ void gcn2_k(const float* __restrict__ g2b) {
    int lane = threadIdx.x & 31;
    int n = blockIdx.x * (blockDim.x >> 5) + (threadIdx.x >> 5);
    if (n >= NN) return;
    int base = d_off[n], end = d_off[n + 1];
    float a0 = 0.f, a1 = 0.f, a2 = 0.f, a3 = 0.f;
    int k = base;
    for (; k + 4 <= end; k += 4) {
        int r0 = __ldg(&d_rows[k + 0]), r1 = __ldg(&d_rows[k + 1]);
        int r2 = __ldg(&d_rows[k + 2]), r3 = __ldg(&d_rows[k + 3]);
        a0 += d_y[r0 * HH + lane]; a1 += d_y[r1 * HH + lane];
        a2 += d_y[r2 * HH + lane]; a3 += d_y[r3 * HH + lane];
    }
    for (; k < end; k++) a0 += d_y[__ldg(&d_rows[k]) * HH + lane];
    float acc = (a0 + a1) + (a2 + a3);
    float dv = d_dinv[n];
    float v = dv * acc + dv * dv * d_xw2[n * HH + lane] + g2b[lane];
    d_h2[n * HH + lane] = fmaxf(v, 0.f);
}

// ---------------- mean pool (per graph, no atomics) + classifier ----------------
__global__ void pool_cls_k(const float* __restrict__ clsW, const float* __restrict__ clsb,
                           float* __restrict__ out) {
    __shared__ float red[8][HH];
    __shared__ float pooled[HH];
    int g = blockIdx.x;
    int lane = threadIdx.x & 31, w = threadIdx.x >> 5;
    int s = d_gstart[g], e = d_gstart[g + 1];
    float acc = 0.f;
    for (int n = s + w; n < e; n += 8) acc += d_h2[n * HH + lane];
    red[w][lane] = acc;
    __syncthreads();
    if (w == 0) {
        float v = red[0][lane];
        #pragma unroll
        for (int i = 1; i < 8; i++) v += red[i][lane];
        float cnt = fmaxf((float)(e - s), 1.f);
        pooled[lane] = v / cnt;
    }
    __syncthreads();
    if (threadIdx.x < CC) {
        float sres = clsb[threadIdx.x];
        #pragma unroll
        for (int k2 = 0; k2 < HH; k2++) sres += pooled[k2] * clsW[k2 * CC + threadIdx.x];
        out[g * CC + threadIdx.x] = sres;
    }
}

// ---------------- launch ----------------
extern "C" void kernel_launch(void* const* d_in, const int* in_sizes, int n_in,
                              void* d_out, int out_size) {
    const float* x     = (const float*)d_in[0];
    const int*   ei    = (const int*)d_in[1];
    const int*   row   = ei;
    const int*   col   = ei + EE;
    const int*   batch = (const int*)d_in[2];
    const float* fW    = (const float*)d_in[3];
    const float* fb    = (const float*)d_in[4];
    const float* W1    = (const float*)d_in[5];
    const float* b1    = (const float*)d_in[6];
    const float* W2    = (const float*)d_in[7];
    const float* b2    = (const float*)d_in[8];
    const float* g1W   = (const float*)d_in[9];
    const float* g1b   = (const float*)d_in[10];
    const float* g2W   = (const float*)d_in[11];
    const float* g2b   = (const float*)d_in[12];
    const float* clsW  = (const float*)d_in[13];
    const float* clsb  = (const float*)d_in[14];
    float* out = (float*)d_out;

    const int TB = 256;
    const int gridE  = (EE + TB - 1) / TB;          // 6250
    const int gridN  = (NN + TB - 1) / TB;          // 391
    const int gridNH = (NN * HH + TB - 1) / TB;     // 12500

    setup_k<<<64, TB>>>(fW, fb, W1, b1, W2, b2, g1W);
    zero_k<<<128, TB>>>();
    hist_k<<<gridE, TB>>>(col);
    gstart_k<<<gridN, TB>>>(batch);
    scanA_k<<<NBLK, 1024>>>();
    scanB_k<<<1, 32>>>();
    scanC_k<<<NBLK, 1024>>>();
    fill_k<<<gridE, TB>>>(row, col);
    init_k<<<gridNH, TB>>>(x, g1W);
    edge_k<<<1184, TB>>>();
    gemm_k<<<gridN, TB>>>();
    gcn1_k<<<gridNH, TB>>>(g1b);
    xw2_k<<<gridNH, TB>>>(g2W);
    gcn2_k<<<gridNH, TB>>>(g2b);
    pool_cls_k<<<GG, TB>>>(clsW, clsb, out);
}